// round 1
// baseline (speedup 1.0000x reference)
#include <cuda_runtime.h>
#include <cuda_bf16.h>
#include <cstdint>

// QuantizedLinear: out[64,11008] = x[64,4096] @ (Wq*scale)^T + bias
// Strategy: bf16 tensor-core GEMM with x split into (hi,lo) bf16 interleaved
// along K (K_eff=8192), W duplicated across each (hi,lo) pair. Products are
// exact in bf16 (int8 weights and both splits are exactly representable);
// fp32 accumulation inside mma.sync. Fused int32->bf16 dequant in smem fill.

#define M_DIM 64
#define K_DIM 4096
#define N_DIM 11008

#define BN 64          // output cols per CTA
#define BKR 64         // real K per tile
#define BKE 128        // effective K per tile (hi/lo interleaved)
#define THREADS 256
#define SA_STRIDE (BKE + 8)   // bf16 elems per row (pad to kill bank conflicts)
#define SB_STRIDE (BKE + 8)

__device__ __forceinline__ unsigned pack_bf2(__nv_bfloat16 a, __nv_bfloat16 b) {
    return (unsigned)__bfloat16_as_ushort(a) | ((unsigned)__bfloat16_as_ushort(b) << 16);
}

__global__ __launch_bounds__(THREADS, 2)
void qlinear_kernel(const float* __restrict__ x,
                    const int*   __restrict__ wq,
                    const float* __restrict__ wscale,
                    const float* __restrict__ bias,
                    float*       __restrict__ out)
{
    __shared__ __align__(16) __nv_bfloat16 As[M_DIM * SA_STRIDE];  // x hi/lo, [m][keff]
    __shared__ __align__(16) __nv_bfloat16 Bs[BN   * SB_STRIDE];   // w dup,   [n][keff]

    const int tid  = threadIdx.x;
    const int bn0  = blockIdx.x * BN;

    // ---- global load mapping (per tile): each thread 4x float4 of x, 4x int4 of W
    const int gcol4 = tid & 15;        // float4/int4 column within 64-wide tile
    const int grow  = tid >> 4;        // base row (16 rows per pass, 4 passes)

    float4 xr[4];
    int4   wr[4];

    const float* xg = x  + grow * K_DIM + gcol4 * 4;
    const int*   wg = wq + (bn0 + grow) * K_DIM + gcol4 * 4;

    // prefetch tile 0
    #pragma unroll
    for (int p = 0; p < 4; ++p) {
        xr[p] = *(const float4*)(xg + p * 16 * K_DIM);
        wr[p] = *(const int4*)  (wg + p * 16 * K_DIM);
    }

    // ---- compute mapping
    const int lane   = tid & 31;
    const int wid    = tid >> 5;
    const int warp_m = wid & 3;        // 4 m-tiles of 16 rows
    const int warp_n = wid >> 2;       // 2 n-tiles of 32 cols
    const int g      = lane >> 2;      // 0..7
    const int qp     = lane & 3;       // 0..3

    float acc[4][4];
    #pragma unroll
    for (int f = 0; f < 4; ++f)
        #pragma unroll
        for (int j = 0; j < 4; ++j) acc[f][j] = 0.0f;

    const __nv_bfloat16* Abase = As + (16 * warp_m + g) * SA_STRIDE + qp * 2;
    const __nv_bfloat16* Bbase = Bs + (32 * warp_n + g) * SB_STRIDE + qp * 2;

    const int NT = K_DIM / BKR;  // 64 tiles
    for (int kt = 0; kt < NT; ++kt) {
        // ---- store prefetched regs -> smem (with dequant / hi-lo split)
        {
            unsigned smA = (grow) * SA_STRIDE + gcol4 * 8;  // elem offset
            unsigned smB = (grow) * SB_STRIDE + gcol4 * 8;
            #pragma unroll
            for (int p = 0; p < 4; ++p) {
                // x: 4 floats -> (hi,lo)x4 = 8 bf16
                float fx[4] = {xr[p].x, xr[p].y, xr[p].z, xr[p].w};
                uint4 pa;
                {
                    __nv_bfloat16 h0 = __float2bfloat16_rn(fx[0]);
                    __nv_bfloat16 l0 = __float2bfloat16_rn(fx[0] - __bfloat162float(h0));
                    __nv_bfloat16 h1 = __float2bfloat16_rn(fx[1]);
                    __nv_bfloat16 l1 = __float2bfloat16_rn(fx[1] - __bfloat162float(h1));
                    __nv_bfloat16 h2 = __float2bfloat16_rn(fx[2]);
                    __nv_bfloat16 l2 = __float2bfloat16_rn(fx[2] - __bfloat162float(h2));
                    __nv_bfloat16 h3 = __float2bfloat16_rn(fx[3]);
                    __nv_bfloat16 l3 = __float2bfloat16_rn(fx[3] - __bfloat162float(h3));
                    pa.x = pack_bf2(h0, l0); pa.y = pack_bf2(h1, l1);
                    pa.z = pack_bf2(h2, l2); pa.w = pack_bf2(h3, l3);
                }
                *(uint4*)(As + smA + p * 16 * SA_STRIDE) = pa;

                // w: 4 ints -> duplicated bf16 pairs
                uint4 pb;
                {
                    __nv_bfloat16 w0 = __float2bfloat16_rn((float)wr[p].x);
                    __nv_bfloat16 w1 = __float2bfloat16_rn((float)wr[p].y);
                    __nv_bfloat16 w2 = __float2bfloat16_rn((float)wr[p].z);
                    __nv_bfloat16 w3 = __float2bfloat16_rn((float)wr[p].w);
                    pb.x = pack_bf2(w0, w0); pb.y = pack_bf2(w1, w1);
                    pb.z = pack_bf2(w2, w2); pb.w = pack_bf2(w3, w3);
                }
                *(uint4*)(Bs + smB + p * 16 * SB_STRIDE) = pb;
            }
        }
        __syncthreads();

        // ---- prefetch next tile (overlaps mma below)
        if (kt + 1 < NT) {
            const float* xn = xg + (kt + 1) * BKR;
            const int*   wn = wg + (kt + 1) * BKR;
            #pragma unroll
            for (int p = 0; p < 4; ++p) {
                xr[p] = *(const float4*)(xn + p * 16 * K_DIM);
                wr[p] = *(const int4*)  (wn + p * 16 * K_DIM);
            }
        }

        // ---- compute: 8 k16 steps over BKE=128
        #pragma unroll
        for (int ks = 0; ks < 8; ++ks) {
            const int ke = ks * 16;
            unsigned a0 = *(const unsigned*)(Abase + ke);
            unsigned a1 = *(const unsigned*)(Abase + ke + 8 * SA_STRIDE);
            unsigned a2 = *(const unsigned*)(Abase + ke + 8);
            unsigned a3 = *(const unsigned*)(Abase + ke + 8 * SA_STRIDE + 8);
            #pragma unroll
            for (int fn = 0; fn < 4; ++fn) {
                const __nv_bfloat16* bp = Bbase + fn * 8 * SB_STRIDE + ke;
                unsigned b0 = *(const unsigned*)(bp);
                unsigned b1 = *(const unsigned*)(bp + 8);
                asm volatile(
                    "mma.sync.aligned.m16n8k16.row.col.f32.bf16.bf16.f32 "
                    "{%0,%1,%2,%3}, {%4,%5,%6,%7}, {%8,%9}, {%0,%1,%2,%3};\n"
                    : "+f"(acc[fn][0]), "+f"(acc[fn][1]),
                      "+f"(acc[fn][2]), "+f"(acc[fn][3])
                    : "r"(a0), "r"(a1), "r"(a2), "r"(a3), "r"(b0), "r"(b1));
            }
        }
        __syncthreads();
    }

    // ---- epilogue: out = scale * acc + bias
    const float s = wscale[0];
    const int m0 = 16 * warp_m + g;
    #pragma unroll
    for (int fn = 0; fn < 4; ++fn) {
        const int n = bn0 + 32 * warp_n + 8 * fn + qp * 2;
        float b0 = bias[n];
        float b1 = bias[n + 1];
        float2 r0 = make_float2(s * acc[fn][0] + b0, s * acc[fn][1] + b1);
        float2 r1 = make_float2(s * acc[fn][2] + b0, s * acc[fn][3] + b1);
        *(float2*)(out + (size_t)m0 * N_DIM + n)       = r0;
        *(float2*)(out + (size_t)(m0 + 8) * N_DIM + n) = r1;
    }
}

extern "C" void kernel_launch(void* const* d_in, const int* in_sizes, int n_in,
                              void* d_out, int out_size) {
    const float* x      = (const float*)d_in[0];
    const int*   wq     = (const int*)  d_in[1];
    const float* wscale = (const float*)d_in[2];
    const float* bias   = (const float*)d_in[3];
    float*       out    = (float*)d_out;

    dim3 grid(N_DIM / BN);   // 172
    dim3 block(THREADS);
    qlinear_kernel<<<grid, block>>>(x, wq, wscale, bias, out);
}

// round 3
// speedup vs baseline: 1.9464x; 1.9464x over previous
#include <cuda_runtime.h>
#include <cuda_bf16.h>
#include <cstdint>

// out[64,11008] = x[64,4096] @ (Wq*scale)^T + bias
// v2b: split-K(8) HMMA GEMM (fixes R2 macro compile error).
//  - x preconverted once to hi/lo bf16 (exact products, fp32 accum): keff = 8192
//  - keff ordering is PERMUTED so each thread's B fragment needs 4 contiguous
//    int32 (one LDG.128) and b1 == b0 (hi/lo halves reuse the same W values).
//  - A: cp.async double-buffered smem + ldmatrix.  B: global -> regs directly.
//  - partials in __device__ scratch, reduce kernel adds bias.

#define M_DIM 64
#define K_DIM 4096
#define N_DIM 11008

#define SPLITS 8
#define KSR    512          // real k per split
#define BKR    64           // real k per stage
#define NST    (KSR / BKR)  // 8 stages per CTA
#define BKE    128          // effective k per stage (hi/lo)
#define SA     136          // smem row stride in bf16 elems (128 + 8 pad)
#define BN     128          // CTA n-tile
#define THREADS 256

__device__ __align__(16) __nv_bfloat16 g_Axl[M_DIM * 8192];          // 1 MB
__device__ float g_part[SPLITS * M_DIM * N_DIM];                     // 22.5 MB

__device__ __forceinline__ unsigned pack_bf2(__nv_bfloat16 a, __nv_bfloat16 b) {
    return (unsigned)__bfloat16_as_ushort(a) | ((unsigned)__bfloat16_as_ushort(b) << 16);
}

// ---------------------------------------------------------------------------
// Kernel 1: x[64,4096] f32 -> g_Axl[64,8192] bf16, permuted hi/lo layout.
// keff local (per 128-block "stage"): slot(s,b,qp,e) = s*16 + b*8 + 2qp + e
//   maps to real k = 16*(s>>1) + 4*qp + 2*(s&1) + e ; b=0 -> hi(x), b=1 -> lo(x)
// ---------------------------------------------------------------------------
__global__ void convx_kernel(const float* __restrict__ x) {
    int t = blockIdx.x * blockDim.x + threadIdx.x;   // 0..4095
    int m = t >> 6;
    int stage = t & 63;
    const float* xr = x + m * K_DIM + stage * 64;

    unsigned u[64];
    #pragma unroll
    for (int s = 0; s < 8; ++s) {
        #pragma unroll
        for (int qp = 0; qp < 4; ++qp) {
            int k0 = 16 * (s >> 1) + 4 * qp + 2 * (s & 1);
            float a = xr[k0], c = xr[k0 + 1];
            __nv_bfloat16 ha = __float2bfloat16_rn(a);
            __nv_bfloat16 hc = __float2bfloat16_rn(c);
            float la = a - __bfloat162float(ha);
            float lc = c - __bfloat162float(hc);
            u[s * 8 + qp]     = pack_bf2(ha, hc);
            u[s * 8 + 4 + qp] = pack_bf2(__float2bfloat16_rn(la), __float2bfloat16_rn(lc));
        }
    }
    uint4* dst = (uint4*)(g_Axl + m * 8192 + stage * 128);
    #pragma unroll
    for (int i = 0; i < 16; ++i) dst[i] = ((const uint4*)u)[i];
}

// ---------------------------------------------------------------------------
// Kernel 2: split-K GEMM.  CTA: 8 warps, warp = M64 x N16.  grid (86, 8).
// ---------------------------------------------------------------------------
#define MMA16816(d, a0, a1, a2, a3, b)                                          \
    asm volatile(                                                               \
        "mma.sync.aligned.m16n8k16.row.col.f32.bf16.bf16.f32 "                  \
        "{%0,%1,%2,%3}, {%4,%5,%6,%7}, {%8,%9}, {%0,%1,%2,%3};\n"               \
        : "+f"(d[0]), "+f"(d[1]), "+f"(d[2]), "+f"(d[3])                        \
        : "r"(a0), "r"(a1), "r"(a2), "r"(a3), "r"(b), "r"(b))

__device__ __forceinline__ void issue_a(uint32_t adst0, const __nv_bfloat16* agsrc,
                                        int kt, int buf) {
    #pragma unroll
    for (int j = 0; j < 4; ++j) {
        uint32_t d = adst0 + buf * (M_DIM * SA * 2) + j * (16 * SA * 2);
        const void* s = agsrc + kt * BKE + (size_t)j * 16 * 8192;
        asm volatile("cp.async.ca.shared.global [%0], [%1], 16;\n"
                     :: "r"(d), "l"(s));
    }
}

__global__ __launch_bounds__(THREADS, 2)
void qgemm_kernel(const int* __restrict__ wq, float* __restrict__ part) {
    __shared__ __align__(16) __nv_bfloat16 As[2][M_DIM * SA];

    const int tid  = threadIdx.x;
    const int lane = tid & 31;
    const int wid  = tid >> 5;
    const int qp   = lane & 3;
    const int g    = lane >> 2;
    const int bn0   = blockIdx.x * BN;
    const int split = blockIdx.y;

    uint32_t sb;
    { void* p = (void*)As;
      asm("{.reg .u64 t; cvta.to.shared.u64 t, %1; cvt.u32.u64 %0, t;}"
          : "=r"(sb) : "l"(p)); }

    // ---- A cp.async mapping: thread copies 4 x 16B per stage
    const int acol = tid & 15;            // 16B chunk within keff-128 row
    const int arow = tid >> 4;            // base row, +16 per j
    const __nv_bfloat16* agsrc = g_Axl + (size_t)arow * 8192 + split * (KSR * 2) + acol * 8;
    const uint32_t adst0 = sb + (uint32_t)((arow * SA + acol * 8) * 2);

    // ---- B pointers: nfrag f row = bn0 + wid*16 + f*8 + g
    const int* wg0 = wq + (size_t)(bn0 + wid * 16 + g) * K_DIM + split * KSR + 4 * qp;
    const int* wg1 = wg0 + (size_t)8 * K_DIM;

    int4 Bn[2][4];

    // ---- prologue: stage 0
    issue_a(adst0, agsrc, 0, 0);
    asm volatile("cp.async.commit_group;\n");
    #pragma unroll
    for (int j = 0; j < 4; ++j) {
        Bn[0][j] = *(const int4*)(wg0 + 16 * j);
        Bn[1][j] = *(const int4*)(wg1 + 16 * j);
    }

    float acc[4][2][4];
    #pragma unroll
    for (int a = 0; a < 4; ++a)
        #pragma unroll
        for (int b = 0; b < 2; ++b)
            #pragma unroll
            for (int c = 0; c < 4; ++c) acc[a][b][c] = 0.0f;

    const uint32_t aptr = sb + (uint32_t)(((lane & 15) * SA + (lane >> 4) * 8) * 2);

    for (int kt = 0; kt < NST; ++kt) {
        if (kt + 1 < NST) issue_a(adst0, agsrc, kt + 1, (kt + 1) & 1);
        asm volatile("cp.async.commit_group;\n");
        if (kt + 1 < NST) asm volatile("cp.async.wait_group 1;\n");
        else              asm volatile("cp.async.wait_group 0;\n");
        __syncthreads();

        const uint32_t abuf = aptr + (kt & 1) * (M_DIM * SA * 2);
        const int* nw0 = wg0 + (kt + 1) * BKR;
        const int* nw1 = wg1 + (kt + 1) * BKR;
        const bool pf = (kt + 1 < NST);

        #pragma unroll
        for (int s = 0; s < 8; ++s) {
            const int j = s >> 1;
            int v0x, v0y, v1x, v1y;
            if ((s & 1) == 0) { v0x = Bn[0][j].x; v0y = Bn[0][j].y;
                                v1x = Bn[1][j].x; v1y = Bn[1][j].y; }
            else              { v0x = Bn[0][j].z; v0y = Bn[0][j].w;
                                v1x = Bn[1][j].z; v1y = Bn[1][j].w; }
            float f0 = (float)v0x, f1 = (float)v0y;
            float f2 = (float)v1x, f3 = (float)v1y;
            unsigned bb0, bb1;
            asm("cvt.rn.bf16x2.f32 %0, %1, %2;" : "=r"(bb0) : "f"(f1), "f"(f0));
            asm("cvt.rn.bf16x2.f32 %0, %1, %2;" : "=r"(bb1) : "f"(f3), "f"(f2));

            // refill Bn[*][j] for next stage once consumed (odd s)
            if ((s & 1) == 1 && pf) {
                Bn[0][j] = *(const int4*)(nw0 + 16 * j);
                Bn[1][j] = *(const int4*)(nw1 + 16 * j);
            }

            #pragma unroll
            for (int fm = 0; fm < 4; ++fm) {
                unsigned a0, a1, a2, a3;
                asm volatile(
                    "ldmatrix.sync.aligned.m8n8.x4.shared.b16 {%0,%1,%2,%3}, [%4];\n"
                    : "=r"(a0), "=r"(a1), "=r"(a2), "=r"(a3)
                    : "r"(abuf + fm * (16 * SA * 2) + s * 32));
                MMA16816(acc[fm][0], a0, a1, a2, a3, bb0);
                MMA16816(acc[fm][1], a0, a1, a2, a3, bb1);
            }
        }
        __syncthreads();
    }

    // ---- epilogue: partial (no scale/bias yet) to scratch
    float* P = part + (size_t)split * (M_DIM * N_DIM);
    #pragma unroll
    for (int fm = 0; fm < 4; ++fm) {
        const int m0 = fm * 16 + g;
        #pragma unroll
        for (int fn = 0; fn < 2; ++fn) {
            const int n = bn0 + wid * 16 + fn * 8 + 2 * qp;
            *(float2*)(P + (size_t)m0 * N_DIM + n) =
                make_float2(acc[fm][fn][0], acc[fm][fn][1]);
            *(float2*)(P + (size_t)(m0 + 8) * N_DIM + n) =
                make_float2(acc[fm][fn][2], acc[fm][fn][3]);
        }
    }
}

// ---------------------------------------------------------------------------
// Kernel 3: out = scale * (sum of partials) + bias     (float2 vectorized)
// ---------------------------------------------------------------------------
__global__ void reduce_kernel(const float* __restrict__ wscale,
                              const float* __restrict__ bias,
                              float* __restrict__ out) {
    const int TOT2 = M_DIM * N_DIM / 2;
    int i = blockIdx.x * blockDim.x + threadIdx.x;
    if (i >= TOT2) return;
    const float2* P = (const float2*)g_part;
    const int S2 = TOT2;
    float sx = 0.0f, sy = 0.0f;
    #pragma unroll
    for (int s = 0; s < SPLITS; ++s) {
        float2 v = P[i + (size_t)s * S2];
        sx += v.x; sy += v.y;
    }
    const float sc = wscale[0];
    int n = (2 * i) % N_DIM;
    float2 bs = *(const float2*)(bias + n);
    ((float2*)out)[i] = make_float2(sc * sx + bs.x, sc * sy + bs.y);
}

extern "C" void kernel_launch(void* const* d_in, const int* in_sizes, int n_in,
                              void* d_out, int out_size) {
    const float* x      = (const float*)d_in[0];
    const int*   wq     = (const int*)  d_in[1];
    const float* wscale = (const float*)d_in[2];
    const float* bias   = (const float*)d_in[3];
    float*       out    = (float*)d_out;

    float* part;
    cudaGetSymbolAddress((void**)&part, g_part);

    convx_kernel<<<16, 256>>>(x);
    qgemm_kernel<<<dim3(N_DIM / BN, SPLITS), THREADS>>>(wq, part);
    reduce_kernel<<<(M_DIM * N_DIM / 2 + 255) / 256, 256>>>(wscale, bias, out);
}

// round 4
// speedup vs baseline: 2.3127x; 1.1882x over previous
#include <cuda_runtime.h>
#include <cuda_bf16.h>
#include <cstdint>

// out[64,11008] = x[64,4096] @ (Wq*scale)^T + bias
// v3: same split-K(8) HMMA GEMM as v2b; convx re-parallelized (16 floats/thread,
//     128 blocks) and reduce vectorized to float4.

#define M_DIM 64
#define K_DIM 4096
#define N_DIM 11008

#define SPLITS 8
#define KSR    512          // real k per split
#define BKR    64           // real k per stage
#define NST    (KSR / BKR)  // 8 stages per CTA
#define BKE    128          // effective k per stage (hi/lo)
#define SA     136          // smem row stride in bf16 elems (128 + 8 pad)
#define BN     128          // CTA n-tile
#define THREADS 256

__device__ __align__(16) __nv_bfloat16 g_Axl[M_DIM * 8192];          // 1 MB
__device__ float g_part[SPLITS * M_DIM * N_DIM];                     // 22.5 MB

__device__ __forceinline__ unsigned pack_bf2(__nv_bfloat16 a, __nv_bfloat16 b) {
    return (unsigned)__bfloat16_as_ushort(a) | ((unsigned)__bfloat16_as_ushort(b) << 16);
}

// ---------------------------------------------------------------------------
// Kernel 1: x[64,4096] f32 -> g_Axl[64,8192] bf16, permuted hi/lo layout.
// keff local (per 128-slot stage block): slot(s,b,qp,e) = s*16 + b*8 + 2qp + e
//   real k = 16*(s>>1) + 4*qp + 2*(s&1) + e ; b=0 -> hi(x), b=1 -> lo(x)
// Thread = (m, stage, j): 16 consecutive floats k in [16j, 16j+16), writes the
// 32-slot keff block [32j, 32j+32) -> fully coalesced 64B read + 64B write.
// 16384 threads = 128 blocks x 128 threads.
// ---------------------------------------------------------------------------
__global__ void convx_kernel(const float* __restrict__ x) {
    int t = blockIdx.x * blockDim.x + threadIdx.x;   // 0..16383
    int m  = t >> 8;          // 0..63
    int st = (t >> 2) & 63;   // stage 0..63
    int j  = t & 3;           // quarter-stage

    float fx[16];
    const float4* src = (const float4*)(x + m * K_DIM + st * 64 + j * 16);
    #pragma unroll
    for (int q = 0; q < 4; ++q) ((float4*)fx)[q] = src[q];

    unsigned u[16];
    #pragma unroll
    for (int sp = 0; sp < 2; ++sp) {          // s & 1
        #pragma unroll
        for (int qp = 0; qp < 4; ++qp) {
            int kl = 4 * qp + 2 * sp;         // local k (0..15), covers e=0,1
            float a = fx[kl], c = fx[kl + 1];
            __nv_bfloat16 ha = __float2bfloat16_rn(a);
            __nv_bfloat16 hc = __float2bfloat16_rn(c);
            float la = a - __bfloat162float(ha);
            float lc = c - __bfloat162float(hc);
            u[sp * 8 + qp]     = pack_bf2(ha, hc);
            u[sp * 8 + 4 + qp] = pack_bf2(__float2bfloat16_rn(la), __float2bfloat16_rn(lc));
        }
    }
    uint4* dst = (uint4*)(g_Axl + m * 8192 + st * 128 + j * 32);
    #pragma unroll
    for (int q = 0; q < 4; ++q) dst[q] = ((const uint4*)u)[q];
}

// ---------------------------------------------------------------------------
// Kernel 2: split-K GEMM.  CTA: 8 warps, warp = M64 x N16.  grid (86, 8).
// ---------------------------------------------------------------------------
#define MMA16816(d, a0, a1, a2, a3, b)                                          \
    asm volatile(                                                               \
        "mma.sync.aligned.m16n8k16.row.col.f32.bf16.bf16.f32 "                  \
        "{%0,%1,%2,%3}, {%4,%5,%6,%7}, {%8,%9}, {%0,%1,%2,%3};\n"               \
        : "+f"(d[0]), "+f"(d[1]), "+f"(d[2]), "+f"(d[3])                        \
        : "r"(a0), "r"(a1), "r"(a2), "r"(a3), "r"(b), "r"(b))

__device__ __forceinline__ void issue_a(uint32_t adst0, const __nv_bfloat16* agsrc,
                                        int kt, int buf) {
    #pragma unroll
    for (int j = 0; j < 4; ++j) {
        uint32_t d = adst0 + buf * (M_DIM * SA * 2) + j * (16 * SA * 2);
        const void* s = agsrc + kt * BKE + (size_t)j * 16 * 8192;
        asm volatile("cp.async.ca.shared.global [%0], [%1], 16;\n"
                     :: "r"(d), "l"(s));
    }
}

__global__ __launch_bounds__(THREADS, 2)
void qgemm_kernel(const int* __restrict__ wq, float* __restrict__ part) {
    __shared__ __align__(16) __nv_bfloat16 As[2][M_DIM * SA];

    const int tid  = threadIdx.x;
    const int lane = tid & 31;
    const int wid  = tid >> 5;
    const int qp   = lane & 3;
    const int g    = lane >> 2;
    const int bn0   = blockIdx.x * BN;
    const int split = blockIdx.y;

    uint32_t sb;
    { void* p = (void*)As;
      asm("{.reg .u64 t; cvta.to.shared.u64 t, %1; cvt.u32.u64 %0, t;}"
          : "=r"(sb) : "l"(p)); }

    // ---- A cp.async mapping: thread copies 4 x 16B per stage
    const int acol = tid & 15;            // 16B chunk within keff-128 row
    const int arow = tid >> 4;            // base row, +16 per j
    const __nv_bfloat16* agsrc = g_Axl + (size_t)arow * 8192 + split * (KSR * 2) + acol * 8;
    const uint32_t adst0 = sb + (uint32_t)((arow * SA + acol * 8) * 2);

    // ---- B pointers: nfrag f row = bn0 + wid*16 + f*8 + g
    const int* wg0 = wq + (size_t)(bn0 + wid * 16 + g) * K_DIM + split * KSR + 4 * qp;
    const int* wg1 = wg0 + (size_t)8 * K_DIM;

    int4 Bn[2][4];

    // ---- prologue: stage 0
    issue_a(adst0, agsrc, 0, 0);
    asm volatile("cp.async.commit_group;\n");
    #pragma unroll
    for (int j = 0; j < 4; ++j) {
        Bn[0][j] = *(const int4*)(wg0 + 16 * j);
        Bn[1][j] = *(const int4*)(wg1 + 16 * j);
    }

    float acc[4][2][4];
    #pragma unroll
    for (int a = 0; a < 4; ++a)
        #pragma unroll
        for (int b = 0; b < 2; ++b)
            #pragma unroll
            for (int c = 0; c < 4; ++c) acc[a][b][c] = 0.0f;

    const uint32_t aptr = sb + (uint32_t)(((lane & 15) * SA + (lane >> 4) * 8) * 2);

    for (int kt = 0; kt < NST; ++kt) {
        if (kt + 1 < NST) issue_a(adst0, agsrc, kt + 1, (kt + 1) & 1);
        asm volatile("cp.async.commit_group;\n");
        if (kt + 1 < NST) asm volatile("cp.async.wait_group 1;\n");
        else              asm volatile("cp.async.wait_group 0;\n");
        __syncthreads();

        const uint32_t abuf = aptr + (kt & 1) * (M_DIM * SA * 2);
        const int* nw0 = wg0 + (kt + 1) * BKR;
        const int* nw1 = wg1 + (kt + 1) * BKR;
        const bool pf = (kt + 1 < NST);

        #pragma unroll
        for (int s = 0; s < 8; ++s) {
            const int j = s >> 1;
            int v0x, v0y, v1x, v1y;
            if ((s & 1) == 0) { v0x = Bn[0][j].x; v0y = Bn[0][j].y;
                                v1x = Bn[1][j].x; v1y = Bn[1][j].y; }
            else              { v0x = Bn[0][j].z; v0y = Bn[0][j].w;
                                v1x = Bn[1][j].z; v1y = Bn[1][j].w; }
            float f0 = (float)v0x, f1 = (float)v0y;
            float f2 = (float)v1x, f3 = (float)v1y;
            unsigned bb0, bb1;
            asm("cvt.rn.bf16x2.f32 %0, %1, %2;" : "=r"(bb0) : "f"(f1), "f"(f0));
            asm("cvt.rn.bf16x2.f32 %0, %1, %2;" : "=r"(bb1) : "f"(f3), "f"(f2));

            // refill Bn[*][j] for next stage once consumed (odd s)
            if ((s & 1) == 1 && pf) {
                Bn[0][j] = *(const int4*)(nw0 + 16 * j);
                Bn[1][j] = *(const int4*)(nw1 + 16 * j);
            }

            #pragma unroll
            for (int fm = 0; fm < 4; ++fm) {
                unsigned a0, a1, a2, a3;
                asm volatile(
                    "ldmatrix.sync.aligned.m8n8.x4.shared.b16 {%0,%1,%2,%3}, [%4];\n"
                    : "=r"(a0), "=r"(a1), "=r"(a2), "=r"(a3)
                    : "r"(abuf + fm * (16 * SA * 2) + s * 32));
                MMA16816(acc[fm][0], a0, a1, a2, a3, bb0);
                MMA16816(acc[fm][1], a0, a1, a2, a3, bb1);
            }
        }
        __syncthreads();
    }

    // ---- epilogue: partial (no scale/bias yet) to scratch
    float* P = part + (size_t)split * (M_DIM * N_DIM);
    #pragma unroll
    for (int fm = 0; fm < 4; ++fm) {
        const int m0 = fm * 16 + g;
        #pragma unroll
        for (int fn = 0; fn < 2; ++fn) {
            const int n = bn0 + wid * 16 + fn * 8 + 2 * qp;
            *(float2*)(P + (size_t)m0 * N_DIM + n) =
                make_float2(acc[fm][fn][0], acc[fm][fn][1]);
            *(float2*)(P + (size_t)(m0 + 8) * N_DIM + n) =
                make_float2(acc[fm][fn][2], acc[fm][fn][3]);
        }
    }
}

// ---------------------------------------------------------------------------
// Kernel 3: out = scale * (sum of partials) + bias     (float4 vectorized)
// ---------------------------------------------------------------------------
__global__ void reduce_kernel(const float* __restrict__ wscale,
                              const float* __restrict__ bias,
                              float* __restrict__ out) {
    const int TOT4 = M_DIM * N_DIM / 4;
    int i = blockIdx.x * blockDim.x + threadIdx.x;
    if (i >= TOT4) return;
    const float4* P = (const float4*)g_part;
    float sx = 0.0f, sy = 0.0f, sz = 0.0f, sw = 0.0f;
    #pragma unroll
    for (int s = 0; s < SPLITS; ++s) {
        float4 v = P[i + (size_t)s * TOT4];
        sx += v.x; sy += v.y; sz += v.z; sw += v.w;
    }
    const float sc = wscale[0];
    int n = (4 * i) % N_DIM;
    float4 bs = *(const float4*)(bias + n);
    ((float4*)out)[i] = make_float4(sc * sx + bs.x, sc * sy + bs.y,
                                    sc * sz + bs.z, sc * sw + bs.w);
}

extern "C" void kernel_launch(void* const* d_in, const int* in_sizes, int n_in,
                              void* d_out, int out_size) {
    const float* x      = (const float*)d_in[0];
    const int*   wq     = (const int*)  d_in[1];
    const float* wscale = (const float*)d_in[2];
    const float* bias   = (const float*)d_in[3];
    float*       out    = (float*)d_out;

    float* part;
    cudaGetSymbolAddress((void**)&part, g_part);

    convx_kernel<<<128, 128>>>(x);
    qgemm_kernel<<<dim3(N_DIM / BN, SPLITS), THREADS>>>(wq, part);
    reduce_kernel<<<(M_DIM * N_DIM / 4 + 255) / 256, 256>>>(wscale, bias, out);
}